// round 6
// baseline (speedup 1.0000x reference)
#include <cuda_runtime.h>
#include <cuda_pipeline.h>

#define FDIM 128
#define NSLOT 12          // smem ring slots per warp (NSLOT-1 rows in flight)
#define NZERO 64          // CTAs that zero the sum region

__device__ unsigned g_zero_flag;   // reset to 0 via 4-byte memset each launch

// Vector reduction (no return) into global memory.
__device__ __forceinline__ void red_add_v4(float* addr, float4 v) {
    asm volatile("red.global.add.v4.f32 [%0], {%1, %2, %3, %4};"
                 :: "l"(addr), "f"(v.x), "f"(v.y), "f"(v.z), "f"(v.w)
                 : "memory");
}

__device__ __forceinline__ float sigmoidf_fast(float x) {
    return 1.0f / (1.0f + __expf(-x));
}

// Spin (acquire) until all zeroing CTAs have released. Called only before the
// first atomic flush of a warp; zeroing CTAs are wave-1 resident -> no deadlock.
__device__ __forceinline__ void wait_zero(bool& ready, unsigned nz) {
    if (!ready) {
        unsigned v;
        for (;;) {
            asm volatile("ld.acquire.gpu.global.u32 %0, [%1];"
                         : "=r"(v) : "l"(&g_zero_flag));
            if (v >= nz) break;
            __nanosleep(64);
        }
        ready = true;
    }
}

// One warp processes CHUNK consecutive rows through a cp.async smem ring.
// Lane l owns features [4l, 4l+4). Sorted segments -> register accumulate,
// flush via red.global only at segment boundaries.
template <int CHUNK, bool WRITE_LOGITS>
__device__ __forceinline__ void run_side(const float4* __restrict__ feats4,
                                         const float* __restrict__ W,
                                         const float* __restrict__ bptr,
                                         const int*   __restrict__ seg,
                                         unsigned n_rows,
                                         float* __restrict__ out_sum,
                                         float* __restrict__ out_logits,
                                         unsigned chunk_idx, unsigned lane,
                                         float4* __restrict__ ring,
                                         bool& ready, unsigned nz)
{
    const unsigned row0 = chunk_idx * CHUNK;
    if (row0 >= n_rows) return;
    const unsigned row_end = min(n_rows, row0 + CHUNK);

    const float4 w4  = reinterpret_cast<const float4*>(W)[lane];
    const float bias = __ldg(bptr);

    // Prologue: put NSLOT-1 rows in flight (empty commits keep accounting exact).
    #pragma unroll
    for (int i = 0; i < NSLOT - 1; ++i) {
        const unsigned r = row0 + i;
        if (r < row_end)
            __pipeline_memcpy_async(&ring[(unsigned)i * 32u + lane],
                                    &feats4[(size_t)r * 32u + lane], 16);
        __pipeline_commit();
    }

    float4 acc = make_float4(0.f, 0.f, 0.f, 0.f);
    int cur = __ldg(seg + row0);

    for (unsigned r = row0; r < row_end; ++r) {
        // After this, group (r-row0) is complete -> slot (r-row0)%NSLOT ready.
        __pipeline_wait_prior(NSLOT - 2);
        const unsigned idx = r - row0;
        const float4 f = ring[(idx % NSLOT) * 32u + lane];

        // Refill the slot consumed LAST iteration (one-full-iteration gap).
        const unsigned nr = r + NSLOT - 1;
        if (nr < row_end)
            __pipeline_memcpy_async(&ring[((nr - row0) % NSLOT) * 32u + lane],
                                    &feats4[(size_t)nr * 32u + lane], 16);
        __pipeline_commit();

        float p = f.x * w4.x + f.y * w4.y + f.z * w4.z + f.w * w4.w;
        #pragma unroll
        for (int o = 16; o > 0; o >>= 1)
            p += __shfl_xor_sync(0xffffffffu, p, o);
        p += bias;
        if (WRITE_LOGITS && lane == 0) out_logits[r] = p;
        const float g = sigmoidf_fast(p);

        const int s = __ldg(seg + r);   // uniform, L1-hot
        if (s != cur) {
            wait_zero(ready, nz);
            red_add_v4(out_sum + (size_t)cur * FDIM + lane * 4, acc);
            acc = make_float4(0.f, 0.f, 0.f, 0.f);
            cur = s;
        }
        acc.x += g * f.x; acc.y += g * f.y; acc.z += g * f.z; acc.w += g * f.w;
    }
    wait_zero(ready, nz);
    red_add_v4(out_sum + (size_t)cur * FDIM + lane * 4, acc);
    __pipeline_wait_prior(0);   // drain before warp exit
}

__global__ __launch_bounds__(256, 4)
void fused_gated_segsum(const float* __restrict__ atom_feats,
                        const float* __restrict__ W_atom,
                        const float* __restrict__ b_atom,
                        const int*   __restrict__ atom_seg,
                        unsigned n_atom, unsigned atom_chunks,
                        const float* __restrict__ vir_feats,
                        const float* __restrict__ W_vir,
                        const float* __restrict__ b_vir,
                        const int*   __restrict__ vir_seg,
                        unsigned n_vir, unsigned vir_chunks,
                        float* __restrict__ sum_atom,
                        float* __restrict__ sum_vir,
                        float* __restrict__ logits,
                        unsigned num_graphs)
{
    __shared__ float4 ring[8][NSLOT * 32];

    const unsigned nz = min((unsigned)NZERO, gridDim.x);

    // First nz CTAs zero the segment-sum region, then release the flag.
    if (blockIdx.x < nz) {
        float4* sums4 = reinterpret_cast<float4*>(sum_atom);  // atom+vir contiguous
        const unsigned total_f4 = num_graphs * 64u;           // num_graphs*256 floats
        const float4 z = make_float4(0.f, 0.f, 0.f, 0.f);
        for (unsigned i = blockIdx.x * blockDim.x + threadIdx.x;
             i < total_f4; i += nz * blockDim.x)
            sums4[i] = z;
        __syncthreads();   // all block stores happen-before the release below
        if (threadIdx.x == 0)
            asm volatile("red.release.gpu.global.add.u32 [%0], 1;"
                         :: "l"(&g_zero_flag) : "memory");
    }

    const unsigned lane = threadIdx.x & 31u;
    const unsigned wid  = threadIdx.x >> 5;
    const unsigned gw   = blockIdx.x * 8u + wid;
    float4* my_ring = &ring[wid][0];
    bool ready = false;

    if (gw < atom_chunks) {
        run_side<128, true>(reinterpret_cast<const float4*>(atom_feats),
                            W_atom, b_atom, atom_seg, n_atom,
                            sum_atom, logits, gw, lane, my_ring, ready, nz);
    } else if (gw < atom_chunks + vir_chunks) {
        run_side<8, false>(reinterpret_cast<const float4*>(vir_feats),
                           W_vir, b_vir, vir_seg, n_vir,
                           sum_vir, nullptr, gw - atom_chunks, lane, my_ring, ready, nz);
    }
}

extern "C" void kernel_launch(void* const* d_in, const int* in_sizes, int n_in,
                              void* d_out, int out_size) {
    const float* atom_feats = (const float*)d_in[0];
    const float* vir_feats  = (const float*)d_in[1];
    const float* W_atom     = (const float*)d_in[2];
    const float* b_atom     = (const float*)d_in[3];
    const float* W_vir      = (const float*)d_in[4];
    const float* b_vir      = (const float*)d_in[5];
    const int*   atom_seg   = (const int*)d_in[6];
    const int*   vir_seg    = (const int*)d_in[7];

    const unsigned n_atom = (unsigned)(in_sizes[0] / FDIM);
    const unsigned n_vir  = (unsigned)(in_sizes[1] / FDIM);
    const unsigned num_graphs = (unsigned)((out_size - (int)n_atom) / (2 * FDIM));

    float* out      = (float*)d_out;
    float* sum_atom = out;
    float* sum_vir  = out + (size_t)num_graphs * FDIM;
    float* logits   = out + (size_t)num_graphs * FDIM * 2;

    // Reset the zero-completion flag (4 bytes) — the 16.8MB zeroing is in-kernel.
    static unsigned* flag_ptr = nullptr;
    if (!flag_ptr) cudaGetSymbolAddress((void**)&flag_ptr, g_zero_flag);
    cudaMemsetAsync(flag_ptr, 0, sizeof(unsigned), 0);

    constexpr unsigned CHUNK_A = 128;
    constexpr unsigned CHUNK_V = 8;
    constexpr int THREADS = 256;   // 8 warps / CTA

    const unsigned atom_chunks = (n_atom + CHUNK_A - 1) / CHUNK_A;
    const unsigned vir_chunks  = (n_vir  + CHUNK_V - 1) / CHUNK_V;
    const unsigned total_warps = atom_chunks + vir_chunks;
    const unsigned blocks = (total_warps + 7u) / 8u;

    fused_gated_segsum<<<blocks, THREADS>>>(
        atom_feats, W_atom, b_atom, atom_seg, n_atom, atom_chunks,
        vir_feats,  W_vir,  b_vir,  vir_seg,  n_vir,  vir_chunks,
        sum_atom, sum_vir, logits, num_graphs);
}

// round 7
// speedup vs baseline: 1.4244x; 1.4244x over previous
#include <cuda_runtime.h>
#include <cuda_bf16.h>

#define FDIM 128
#define NZERO 64           // CTAs that zero the sum region
#define PDIST 8            // L2 prefetch distance in rows

__device__ unsigned g_zero_flag;   // reset to 0 via 4-byte memset each launch

// Vector reduction (no return) into global memory.
__device__ __forceinline__ void red_add_v4(float* addr, float4 v) {
    asm volatile("red.global.add.v4.f32 [%0], {%1, %2, %3, %4};"
                 :: "l"(addr), "f"(v.x), "f"(v.y), "f"(v.z), "f"(v.w)
                 : "memory");
}

__device__ __forceinline__ void prefetch_l2(const void* p) {
    asm volatile("prefetch.global.L2 [%0];" :: "l"(p));
}

__device__ __forceinline__ float sigmoidf_fast(float x) {
    return 1.0f / (1.0f + __expf(-x));
}

// Spin (acquire) until all zeroing CTAs have released. Called only before the
// first atomic flush of a warp; zeroing CTAs are wave-1 resident -> no deadlock.
__device__ __forceinline__ void wait_zero(bool& ready, unsigned nz) {
    if (!ready) {
        unsigned v;
        for (;;) {
            asm volatile("ld.acquire.gpu.global.u32 %0, [%1];"
                         : "=r"(v) : "l"(&g_zero_flag));
            if (v >= nz) break;
            __nanosleep(64);
        }
        ready = true;
    }
}

// One warp processes CHUNK consecutive rows, unrolled by 4 (measured-best).
// Lane l owns features [4l, 4l+4). Sorted segments -> register accumulate,
// flush via red.global only at segment boundaries. L2 prefetch at distance
// PDIST keeps DRAM reads in flight during the shuffle/compute phase.
template <int CHUNK, bool WRITE_LOGITS>
__device__ __forceinline__ void run_side(const float* __restrict__ feats,
                                         const float* __restrict__ W,
                                         const float* __restrict__ bptr,
                                         const int*   __restrict__ seg,
                                         int n_rows,
                                         float* __restrict__ out_sum,
                                         float* __restrict__ out_logits,
                                         int chunk_idx, int lane,
                                         bool& ready, unsigned nz)
{
    long row0 = (long)chunk_idx * CHUNK;
    if (row0 >= n_rows) return;
    const long row_end = min((long)n_rows, row0 + CHUNK);

    const float4 w4  = *reinterpret_cast<const float4*>(W + lane * 4);
    const float bias = __ldg(bptr);

    float4 acc = make_float4(0.f, 0.f, 0.f, 0.f);
    int cur = __ldg(seg + row0);

    long r = row0;
    // Unrolled-by-4 main body: 4 independent load+reduce chains in flight.
    for (; r + 3 < row_end; r += 4) {
        const float4 f0 = *reinterpret_cast<const float4*>(feats + (r + 0) * FDIM + lane * 4);
        const float4 f1 = *reinterpret_cast<const float4*>(feats + (r + 1) * FDIM + lane * 4);
        const float4 f2 = *reinterpret_cast<const float4*>(feats + (r + 2) * FDIM + lane * 4);
        const float4 f3 = *reinterpret_cast<const float4*>(feats + (r + 3) * FDIM + lane * 4);
        const int4  s4  = *reinterpret_cast<const int4*>(seg + r);   // uniform, L1-hit

        // Prefetch rows r+PDIST .. r+PDIST+3 into L2 (no regs, no scoreboard).
        #pragma unroll
        for (int i = 0; i < 4; ++i) {
            const long pr = r + PDIST + i;
            if (pr < (long)n_rows)
                prefetch_l2(feats + pr * FDIM + lane * 4);
        }

        float p0 = f0.x * w4.x + f0.y * w4.y + f0.z * w4.z + f0.w * w4.w;
        float p1 = f1.x * w4.x + f1.y * w4.y + f1.z * w4.z + f1.w * w4.w;
        float p2 = f2.x * w4.x + f2.y * w4.y + f2.z * w4.z + f2.w * w4.w;
        float p3 = f3.x * w4.x + f3.y * w4.y + f3.z * w4.z + f3.w * w4.w;

        // 4 interleaved butterfly chains: SHFL latencies overlap across rows.
        #pragma unroll
        for (int o = 16; o > 0; o >>= 1) {
            p0 += __shfl_xor_sync(0xffffffffu, p0, o);
            p1 += __shfl_xor_sync(0xffffffffu, p1, o);
            p2 += __shfl_xor_sync(0xffffffffu, p2, o);
            p3 += __shfl_xor_sync(0xffffffffu, p3, o);
        }

        const float l0 = p0 + bias, l1 = p1 + bias, l2 = p2 + bias, l3 = p3 + bias;
        if (WRITE_LOGITS && lane == 0) {
            *reinterpret_cast<float4*>(out_logits + r) = make_float4(l0, l1, l2, l3);
        }
        const float g0 = sigmoidf_fast(l0);
        const float g1 = sigmoidf_fast(l1);
        const float g2 = sigmoidf_fast(l2);
        const float g3 = sigmoidf_fast(l3);

        if (s4.w == cur) {
            // Fast path: whole group in current segment (seg sorted, s >= cur).
            acc.x += g0 * f0.x; acc.y += g0 * f0.y; acc.z += g0 * f0.z; acc.w += g0 * f0.w;
            acc.x += g1 * f1.x; acc.y += g1 * f1.y; acc.z += g1 * f1.z; acc.w += g1 * f1.w;
            acc.x += g2 * f2.x; acc.y += g2 * f2.y; acc.z += g2 * f2.z; acc.w += g2 * f2.w;
            acc.x += g3 * f3.x; acc.y += g3 * f3.y; acc.z += g3 * f3.z; acc.w += g3 * f3.w;
        } else {
            if (s4.x != cur) { wait_zero(ready, nz);
                               red_add_v4(out_sum + (long)cur * FDIM + lane * 4, acc);
                               acc = make_float4(0.f,0.f,0.f,0.f); cur = s4.x; }
            acc.x += g0 * f0.x; acc.y += g0 * f0.y; acc.z += g0 * f0.z; acc.w += g0 * f0.w;
            if (s4.y != cur) { wait_zero(ready, nz);
                               red_add_v4(out_sum + (long)cur * FDIM + lane * 4, acc);
                               acc = make_float4(0.f,0.f,0.f,0.f); cur = s4.y; }
            acc.x += g1 * f1.x; acc.y += g1 * f1.y; acc.z += g1 * f1.z; acc.w += g1 * f1.w;
            if (s4.z != cur) { wait_zero(ready, nz);
                               red_add_v4(out_sum + (long)cur * FDIM + lane * 4, acc);
                               acc = make_float4(0.f,0.f,0.f,0.f); cur = s4.z; }
            acc.x += g2 * f2.x; acc.y += g2 * f2.y; acc.z += g2 * f2.z; acc.w += g2 * f2.w;
            if (s4.w != cur) { wait_zero(ready, nz);
                               red_add_v4(out_sum + (long)cur * FDIM + lane * 4, acc);
                               acc = make_float4(0.f,0.f,0.f,0.f); cur = s4.w; }
            acc.x += g3 * f3.x; acc.y += g3 * f3.y; acc.z += g3 * f3.z; acc.w += g3 * f3.w;
        }
    }
    // Scalar tail (not hit for the given shapes, kept for safety).
    for (; r < row_end; ++r) {
        const float4 f = *reinterpret_cast<const float4*>(feats + r * FDIM + lane * 4);
        float p = f.x * w4.x + f.y * w4.y + f.z * w4.z + f.w * w4.w;
        #pragma unroll
        for (int o = 16; o > 0; o >>= 1)
            p += __shfl_xor_sync(0xffffffffu, p, o);
        const float lg = p + bias;
        if (WRITE_LOGITS && lane == 0) out_logits[r] = lg;
        const float g = sigmoidf_fast(lg);
        const int s = __ldg(seg + r);
        if (s != cur) { wait_zero(ready, nz);
                        red_add_v4(out_sum + (long)cur * FDIM + lane * 4, acc);
                        acc = make_float4(0.f,0.f,0.f,0.f); cur = s; }
        acc.x += g * f.x; acc.y += g * f.y; acc.z += g * f.z; acc.w += g * f.w;
    }
    wait_zero(ready, nz);
    red_add_v4(out_sum + (long)cur * FDIM + lane * 4, acc);
}

// Single fused launch: first NZERO CTAs zero the sum region (then release a
// flag), all warps then do atom-side chunks (CHUNK=64, logits) or vir-side
// chunks (CHUNK=8).
__global__ __launch_bounds__(256, 4)
void fused_gated_segsum(const float* __restrict__ atom_feats,
                        const float* __restrict__ W_atom,
                        const float* __restrict__ b_atom,
                        const int*   __restrict__ atom_seg,
                        int n_atom, int atom_chunks,
                        const float* __restrict__ vir_feats,
                        const float* __restrict__ W_vir,
                        const float* __restrict__ b_vir,
                        const int*   __restrict__ vir_seg,
                        int n_vir, int vir_chunks,
                        float* __restrict__ sum_atom,
                        float* __restrict__ sum_vir,
                        float* __restrict__ logits,
                        unsigned num_graphs)
{
    const unsigned nz = min((unsigned)NZERO, gridDim.x);

    // First nz CTAs zero the segment-sum region, then release the flag.
    if (blockIdx.x < nz) {
        float4* sums4 = reinterpret_cast<float4*>(sum_atom);  // atom+vir contiguous
        const unsigned total_f4 = num_graphs * 64u;           // num_graphs*256 floats
        const float4 z = make_float4(0.f, 0.f, 0.f, 0.f);
        for (unsigned i = blockIdx.x * blockDim.x + threadIdx.x;
             i < total_f4; i += nz * blockDim.x)
            sums4[i] = z;
        __syncthreads();   // all block stores happen-before the release below
        if (threadIdx.x == 0)
            asm volatile("red.release.gpu.global.add.u32 [%0], 1;"
                         :: "l"(&g_zero_flag) : "memory");
    }

    const int warp = (int)((blockIdx.x * blockDim.x + threadIdx.x) >> 5);
    const int lane = threadIdx.x & 31;
    bool ready = false;

    if (warp < atom_chunks) {
        run_side<64, true>(atom_feats, W_atom, b_atom, atom_seg, n_atom,
                           sum_atom, logits, warp, lane, ready, nz);
    } else if (warp < atom_chunks + vir_chunks) {
        run_side<8, false>(vir_feats, W_vir, b_vir, vir_seg, n_vir,
                           sum_vir, nullptr, warp - atom_chunks, lane, ready, nz);
    }
}

extern "C" void kernel_launch(void* const* d_in, const int* in_sizes, int n_in,
                              void* d_out, int out_size) {
    const float* atom_feats = (const float*)d_in[0];
    const float* vir_feats  = (const float*)d_in[1];
    const float* W_atom     = (const float*)d_in[2];
    const float* b_atom     = (const float*)d_in[3];
    const float* W_vir      = (const float*)d_in[4];
    const float* b_vir      = (const float*)d_in[5];
    const int*   atom_seg   = (const int*)d_in[6];
    const int*   vir_seg    = (const int*)d_in[7];

    const int n_atom = in_sizes[0] / FDIM;
    const int n_vir  = in_sizes[1] / FDIM;
    const int num_graphs = (out_size - n_atom) / (2 * FDIM);

    float* out      = (float*)d_out;
    float* sum_atom = out;
    float* sum_vir  = out + (size_t)num_graphs * FDIM;
    float* logits   = out + (size_t)num_graphs * FDIM * 2;

    // Reset the zero-completion flag (4 bytes); bulk zeroing happens in-kernel.
    static unsigned* flag_ptr = nullptr;
    if (!flag_ptr) cudaGetSymbolAddress((void**)&flag_ptr, g_zero_flag);
    cudaMemsetAsync(flag_ptr, 0, sizeof(unsigned), 0);

    constexpr int CHUNK_A = 64;
    constexpr int CHUNK_V = 8;
    constexpr int THREADS = 256;   // 8 warps / CTA

    const int atom_chunks = (n_atom + CHUNK_A - 1) / CHUNK_A;
    const int vir_chunks  = (n_vir  + CHUNK_V - 1) / CHUNK_V;
    const int total_warps = atom_chunks + vir_chunks;
    const int blocks = (total_warps + 7) / 8;

    fused_gated_segsum<<<blocks, THREADS>>>(
        atom_feats, W_atom, b_atom, atom_seg, n_atom, atom_chunks,
        vir_feats,  W_vir,  b_vir,  vir_seg,  n_vir,  vir_chunks,
        sum_atom, sum_vir, logits, (unsigned)num_graphs);
}